// round 3
// baseline (speedup 1.0000x reference)
#include <cuda_runtime.h>
#include <math.h>

#define NN     8192
#define MODES  16
#define CH     64
#define BATCH  64
#define ROWS   (BATCH*CH)   /* 4096 */
#define COLS   32           /* 16 cos + 16 sin */
#define KSPLIT 8

// Scratch (allocation-free rule: __device__ globals)
__device__ float g_FB[NN*COLS];                 // basis: [n][c], c<16: cos(2pi k n/N), c>=16: sin
__device__ float g_partial[KSPLIT*ROWS*COLS];   // forward partial sums per K-split
__device__ float g_C2[ROWS*COLS];               // irfft coefficients: [row][c], c<16: A_k, c>=16: B_k

// ---------------------------------------------------------------------------
// Basis table: FB[n][c] = cos/sin(2*pi*k*n/N), exact via double trig on (k*n mod N)
// ---------------------------------------------------------------------------
__global__ void init_basis() {
    int idx = blockIdx.x * blockDim.x + threadIdx.x;
    if (idx >= NN*COLS) return;
    int n = idx >> 5;
    int c = idx & 31;
    int k = c & 15;
    int t = (k * n) & (NN - 1);
    double ang = (double)t * (6.283185307179586476925286766559 / (double)NN);
    g_FB[idx] = (float)((c < 16) ? cos(ang) : sin(ang));
}

// ---------------------------------------------------------------------------
// Forward: CS[row][c] = sum_n x[row][n] * FB[n][c]
// GEMM M=4096, N=32, K=8192. Block tile: 64 rows x 32 cols x K/8 (K-split for
// occupancy: 64 x 8 = 512 blocks). 128 threads, thread tile 4 rows x 4 cols.
// ---------------------------------------------------------------------------
__global__ __launch_bounds__(128) void fwd_dft(const float* __restrict__ x) {
    __shared__ float  xs[64][37];     // [row][k], pad 37 -> conflict-free
    __shared__ float4 bs[32][8];      // [k][c/4]

    const int tid  = threadIdx.x;
    const int row0 = blockIdx.x * 64;
    const int ks   = blockIdx.y;
    const int tr   = tid >> 3;        // 0..15 -> rows 4*tr..4*tr+3
    const int tc   = tid & 7;         // 0..7  -> cols 4*tc..4*tc+3

    float acc[4][4];
    #pragma unroll
    for (int j = 0; j < 4; j++)
        #pragma unroll
        for (int c = 0; c < 4; c++) acc[j][c] = 0.f;

    for (int chunk = 0; chunk < 32; chunk++) {
        const int kbase = ks * 1024 + chunk * 32;

        // stage X tile (64 rows x 32 k) via float4, coalesced
        #pragma unroll
        for (int i = 0; i < 4; i++) {
            int q   = tid + i * 128;
            int row = q >> 3;
            int kq  = q & 7;
            float4 v = *(const float4*)(x + (size_t)(row0 + row) * NN + kbase + 4 * kq);
            xs[row][4*kq + 0] = v.x;
            xs[row][4*kq + 1] = v.y;
            xs[row][4*kq + 2] = v.z;
            xs[row][4*kq + 3] = v.w;
        }
        // stage basis tile (32 k x 32 c), coalesced
        #pragma unroll
        for (int i = 0; i < 2; i++) {
            int q  = tid + i * 128;
            int k  = q >> 3;
            int cq = q & 7;
            bs[k][cq] = *(const float4*)(g_FB + (size_t)(kbase + k) * 32 + 4 * cq);
        }
        __syncthreads();

        #pragma unroll
        for (int k = 0; k < 32; k++) {
            float4 bv = bs[k][tc];
            #pragma unroll
            for (int j = 0; j < 4; j++) {
                float xv = xs[4*tr + j][k];
                acc[j][0] += xv * bv.x;
                acc[j][1] += xv * bv.y;
                acc[j][2] += xv * bv.z;
                acc[j][3] += xv * bv.w;
            }
        }
        __syncthreads();
    }

    #pragma unroll
    for (int j = 0; j < 4; j++) {
        int rg = row0 + 4*tr + j;
        float4 v = make_float4(acc[j][0], acc[j][1], acc[j][2], acc[j][3]);
        *(float4*)(g_partial + ((size_t)ks * ROWS + rg) * 32 + 4 * tc) = v;
    }
}

// ---------------------------------------------------------------------------
// Mix: reduce K-split partials, apply complex weights over in_ch, emit irfft
// coefficients. One block per (k, b); 64 threads = out_ch.
//   c_re = sum_i ( Ccos*Wre + Csin*Wim )      (XF_im = -Csin)
//   c_im = sum_i ( Ccos*Wim - Csin*Wre )
//   A_k = (k==0 ? 1 : 2) * c_re / N ;  B_k = (k==0 ? 0 : -2*c_im/N)
// Weights for fixed k are staged into smem with coalesced loads.
// ---------------------------------------------------------------------------
__global__ __launch_bounds__(64) void mix(const float* __restrict__ wr,
                                          const float* __restrict__ wi) {
    __shared__ float sXc[64], sXs[64];
    __shared__ float sWr[64][64];   // [i][o] for fixed k
    __shared__ float sWi[64][64];
    const int k = blockIdx.x;
    const int b = blockIdx.y;
    const int t = threadIdx.x;

    float xc = 0.f, xsn = 0.f;
    #pragma unroll
    for (int ks = 0; ks < KSPLIT; ks++) {
        const float* p = g_partial + ((size_t)ks * ROWS + b * 64 + t) * 32;
        xc  += p[k];
        xsn += p[16 + k];
    }
    sXc[t] = xc;
    sXs[t] = xsn;

    // stage weight slice [64 i][64 o] for this k. wr layout: (i*64+o)*16+k.
    // Each thread t handles o = t for all i -> load is stride-1024 per i but
    // across threads at fixed i it's stride-16; do it the transposed way:
    // thread t loads i = t row, o = 0..63 -> consecutive-o stride 16. Instead,
    // vectorize over the flat (i*64+o) index: thread covers 64 entries.
    #pragma unroll
    for (int j = 0; j < 64; j++) {
        int io = j * 64 + t;          // i = j, o = t? No: flat index q = j*64+t
        sWr[io >> 6][io & 63] = wr[io * 16 + k];
        sWi[io >> 6][io & 63] = wi[io * 16 + k];
    }
    __syncthreads();

    float cre = 0.f, cim = 0.f;
    #pragma unroll 8
    for (int i = 0; i < 64; i++) {
        float a   = sXc[i];
        float s   = sXs[i];
        float wre = sWr[i][t];
        float wim = sWi[i][t];
        cre += a * wre + s * wim;
        cim += a * wim - s * wre;
    }
    const float invN = 1.0f / (float)NN;
    float A  = (k == 0 ? cre : 2.f * cre) * invN;
    float Bc = (k == 0 ? 0.f : -2.f * cim * invN);
    g_C2[(b * 64 + t) * 32 + k]      = A;
    g_C2[(b * 64 + t) * 32 + 16 + k] = Bc;
}

// ---------------------------------------------------------------------------
// Inverse: y[row][n] = sum_c C2[row][c] * FB[n][c]
// GEMM M=4096, N=8192, K=32. Block tile 64 rows x 128 n. 256 threads,
// thread tile 4 rows x 8 n (n interleaved by 16 for conflict-free LDS).
// ---------------------------------------------------------------------------
__global__ __launch_bounds__(256) void inv_dft(float* __restrict__ y) {
    __shared__ float sC[64][33];     // [row][c]
    __shared__ float sF[32][129];    // [c][n], transposed, pad 129

    const int tid  = threadIdx.x;
    const int n0   = blockIdx.x * 128;
    const int row0 = blockIdx.y * 64;

    #pragma unroll
    for (int i = 0; i < 8; i++) {
        int q = tid + i * 256;
        int c = q & 31;
        int r = q >> 5;
        sC[r][c] = g_C2[(size_t)(row0 + r) * 32 + c];
    }
    #pragma unroll
    for (int i = 0; i < 16; i++) {
        int q = tid + i * 256;
        int c = q & 31;
        int n = q >> 5;
        sF[c][n] = g_FB[(size_t)(n0 + n) * 32 + c];
    }
    __syncthreads();

    const int tr = tid >> 4;   // 0..15 -> rows 4*tr..4*tr+3
    const int tc = tid & 15;   // n = n0 + tc + 16*jj

    float acc[4][8];
    #pragma unroll
    for (int j = 0; j < 4; j++)
        #pragma unroll
        for (int jj = 0; jj < 8; jj++) acc[j][jj] = 0.f;

    #pragma unroll
    for (int c = 0; c < 32; c++) {
        float fv[8];
        #pragma unroll
        for (int jj = 0; jj < 8; jj++) fv[jj] = sF[c][tc + 16 * jj];
        #pragma unroll
        for (int j = 0; j < 4; j++) {
            float cv = sC[4*tr + j][c];
            #pragma unroll
            for (int jj = 0; jj < 8; jj++) acc[j][jj] += cv * fv[jj];
        }
    }

    #pragma unroll
    for (int j = 0; j < 4; j++) {
        size_t base = (size_t)(row0 + 4*tr + j) * NN + n0;
        #pragma unroll
        for (int jj = 0; jj < 8; jj++)
            y[base + tc + 16 * jj] = acc[j][jj];
    }
}

// ---------------------------------------------------------------------------
extern "C" void kernel_launch(void* const* d_in, const int* in_sizes, int n_in,
                              void* d_out, int out_size) {
    const float* x  = (const float*)d_in[0];
    const float* wr = (const float*)d_in[1];
    const float* wi = (const float*)d_in[2];
    float*       y  = (float*)d_out;

    init_basis<<<(NN * COLS + 255) / 256, 256>>>();
    fwd_dft<<<dim3(ROWS / 64, KSPLIT), 128>>>(x);
    mix<<<dim3(MODES, BATCH), 64>>>(wr, wi);
    inv_dft<<<dim3(NN / 128, ROWS / 64), 256>>>(y);
}

// round 4
// speedup vs baseline: 1.6458x; 1.6458x over previous
#include <cuda_runtime.h>
#include <math.h>

#define NN    8192
#define HN    4096
#define QN    2048
#define MODES 16
#define ROWS  4096          /* BATCH*CH */
#define KSPL  8             /* forward m-splits */
#define MSPL  256           /* m per split = QN/KSPL */

// Scratch (__device__ globals: allocation-free rule)
__device__ float g_FBf[QN*32];             // fwd basis, grouped, x0.5 at m=0
__device__ float g_FBi[QN*32];             // inv basis, grouped
__device__ float g_partial[KSPL*ROWS*32];  // fwd partial sums
__device__ float g_C2[ROWS*32];            // irfft coefs, grouped A/B

// Grouped column layout c' = 0..31:
//   j = c'&7, odd = (c'>>3)&1, k = 2j+odd
//   c' 0..7  : cos, even k     c' 8..15 : cos, odd k
//   c' 16..23: sin, even k     c' 24..31: sin, odd k
__global__ void init_basis() {
    int idx = blockIdx.x * blockDim.x + threadIdx.x;
    if (idx >= QN * 32) return;
    int m = idx >> 5, c = idx & 31;
    int j = c & 7;
    int kk = 2 * j + ((c >> 3) & 1);
    int t = (kk * m) & (NN - 1);
    double ang = (double)t * (6.283185307179586476925286766559 / (double)NN);
    float v = (float)((c < 16) ? cos(ang) : sin(ang));
    g_FBi[idx] = v;
    g_FBf[idx] = (m == 0) ? 0.5f * v : v;   // m=0 quartet double-counts x[0],x[4096]
}

// ---------------------------------------------------------------------------
// Forward (folded): CS[row][c'] = sum_{m=0}^{2047} combo_{class(c')}[row][m] * FBf[m][c']
// combos from quartet {m, 4096-m, 4096+m, (8192-m)&8191}:
//   a = (v0+v3)+(v1+v2)   even-cos     cc = (v0+v3)-(v1+v2)  odd-cos
//   b = (v0-v3)+(v2-v1)   even-sin     d  = (v0-v3)-(v2-v1)  odd-sin
// Block: 64 rows, 128 thr, tile 4r x 4c, K-split 8 (256 m each, 8 chunks of 32).
// smem combo layout: cls*2178 + row*34 + m  -> bank = 2*cls + 2*row + m (mod 32),
// conflict-free for compute reads (16 distinct banks, tc-pairs broadcast).
// ---------------------------------------------------------------------------
__global__ __launch_bounds__(128) void fwd_dft(const float* __restrict__ x) {
    __shared__ float  cmb[4 * 2178];
    __shared__ float4 bs[32][8];

    const int tid  = threadIdx.x;
    const int row0 = blockIdx.x * 64;
    const int ms0  = blockIdx.y * MSPL;
    const int tr   = tid >> 3;            // 0..15 -> rows 4*tr..4*tr+3
    const int tc   = tid & 7;             // 0..7  -> cols 4*tc..4*tc+3
    const int cls  = tc >> 1;             // 0..3  class of this thread's columns

    float acc[4][4];
    #pragma unroll
    for (int j = 0; j < 4; j++)
        #pragma unroll
        for (int q = 0; q < 4; q++) acc[j][q] = 0.f;

    for (int ch = 0; ch < 8; ch++) {
        const int m0 = ms0 + ch * 32;

        // ---- stage combos: 64 rows x 8 groups-of-4m, 4 items/thread ----
        #pragma unroll
        for (int i = 0; i < 4; i++) {
            int q   = tid + i * 128;
            int row = q >> 3;
            int g   = q & 7;
            const float* xr = x + (size_t)(row0 + row) * NN;
            int mb = m0 + 4 * g;
            float4 v0 = *(const float4*)(xr + mb);
            float4 v2 = *(const float4*)(xr + HN + mb);
            float v0a[4] = {v0.x, v0.y, v0.z, v0.w};
            float v2a[4] = {v2.x, v2.y, v2.z, v2.w};
            float* base = cmb + row * 34 + 4 * g;
            #pragma unroll
            for (int j = 0; j < 4; j++) {
                int mm = mb + j;
                float v1 = xr[HN - mm];
                float v3 = xr[(NN - mm) & (NN - 1)];
                float p = v0a[j] + v3, q2 = v0a[j] - v3;
                float r = v1 + v2a[j], s = v2a[j] - v1;
                base[0 * 2178 + j] = p + r;   // a   (even-cos)
                base[1 * 2178 + j] = p - r;   // cc  (odd-cos)
                base[2 * 2178 + j] = q2 + s;  // b   (even-sin)
                base[3 * 2178 + j] = q2 - s;  // d   (odd-sin)
            }
        }
        // ---- stage basis tile (32 m x 32 c) ----
        #pragma unroll
        for (int i = 0; i < 2; i++) {
            int q  = tid + i * 128;
            int k  = q >> 3;
            int cq = q & 7;
            bs[k][cq] = *(const float4*)(g_FBf + (size_t)(m0 + k) * 32 + 4 * cq);
        }
        __syncthreads();

        const float* cbase = cmb + cls * 2178;
        #pragma unroll
        for (int m = 0; m < 32; m++) {
            float4 bv = bs[m][tc];
            #pragma unroll
            for (int j = 0; j < 4; j++) {
                float xv = cbase[(4 * tr + j) * 34 + m];
                acc[j][0] += xv * bv.x;
                acc[j][1] += xv * bv.y;
                acc[j][2] += xv * bv.z;
                acc[j][3] += xv * bv.w;
            }
        }
        __syncthreads();
    }

    #pragma unroll
    for (int j = 0; j < 4; j++) {
        int rg = row0 + 4 * tr + j;
        float4 v = make_float4(acc[j][0], acc[j][1], acc[j][2], acc[j][3]);
        *(float4*)(g_partial + ((size_t)blockIdx.y * ROWS + rg) * 32 + 4 * tc) = v;
    }
}

// ---------------------------------------------------------------------------
// Mix: reduce K-splits, add m=2048 boundary term, apply complex weights,
// emit grouped irfft coefficients A (cos) / B (sin).
// ---------------------------------------------------------------------------
__global__ __launch_bounds__(64) void mix(const float* __restrict__ x,
                                          const float* __restrict__ wr,
                                          const float* __restrict__ wi) {
    __shared__ float sXc[64], sXs[64];
    __shared__ float sWr[64][64];
    __shared__ float sWi[64][64];
    const int k = blockIdx.x;
    const int b = blockIdx.y;
    const int t = threadIdx.x;

    const int cA = (k & 1) ? 8 + (k >> 1) : (k >> 1);
    const int cS = cA + 16;

    const int rowi = b * 64 + t;             // in_ch row
    float xc = 0.f, xsn = 0.f;
    #pragma unroll
    for (int ks = 0; ks < KSPL; ks++) {
        const float* p = g_partial + ((size_t)ks * ROWS + rowi) * 32;
        xc  += p[cA];
        xsn += p[cS];
    }
    // m = 2048 boundary quartet {2048,2048,6144,6144}
    {
        float xa = x[(size_t)rowi * NN + QN];
        float xb = x[(size_t)rowi * NN + 3 * QN];
        float sg = ((k >> 1) & 1) ? -1.f : 1.f;
        if (k & 1) xsn += (xa - xb) * sg;     // sin(pi k/2), odd k
        else       xc  += (xa + xb) * sg;     // cos(pi k/2), even k
    }
    sXc[t] = xc;
    sXs[t] = xsn;

    #pragma unroll
    for (int j = 0; j < 64; j++) {
        int io = j * 64 + t;
        sWr[j][t] = wr[io * 16 + k];
        sWi[j][t] = wi[io * 16 + k];
    }
    __syncthreads();

    float cre = 0.f, cim = 0.f;
    #pragma unroll 8
    for (int i = 0; i < 64; i++) {
        float a   = sXc[i];
        float s   = sXs[i];
        float wre = sWr[i][t];
        float wim = sWi[i][t];
        cre += a * wre + s * wim;
        cim += a * wim - s * wre;
    }
    const float invN = 1.0f / (float)NN;
    float A  = (k == 0 ? cre : 2.f * cre) * invN;
    float Bc = (k == 0 ? 0.f : -2.f * cim * invN);
    int rowo = b * 64 + t;                   // out_ch row
    g_C2[(size_t)rowo * 32 + cA] = A;
    g_C2[(size_t)rowo * 32 + cS] = Bc;
}

// ---------------------------------------------------------------------------
// Inverse (folded): per lane (base n), basis in 32 regs; per row: broadcast-LDS
// coefs, 32 FFMA -> 4 partials -> 4 outputs {n, 8192-n, 4096-n, 4096+n}.
// n=0 wrap writes are benign duplicates (sin terms vanish).
// ---------------------------------------------------------------------------
__global__ __launch_bounds__(256) void inv_dft(float* __restrict__ y) {
    __shared__ float sC[64 * 32];
    const int tid  = threadIdx.x;
    const int w    = tid >> 5;
    const int ln   = tid & 31;
    const int row0 = blockIdx.y * 64;
    const int n    = blockIdx.x * 256 + w * 32 + ln;   // 0..2047

    #pragma unroll
    for (int i = 0; i < 2; i++) {
        int q = tid + i * 256;
        *(float4*)(sC + 4 * q) = *(const float4*)(g_C2 + (size_t)row0 * 32 + 4 * q);
    }

    float bas[32];
    #pragma unroll
    for (int i = 0; i < 8; i++) {
        float4 v = *(const float4*)(g_FBi + (size_t)n * 32 + 4 * i);
        bas[4*i+0] = v.x; bas[4*i+1] = v.y; bas[4*i+2] = v.z; bas[4*i+3] = v.w;
    }
    __syncthreads();

    const int nrev = (NN - n) & (NN - 1);
    const int nm   = HN - n;
    const int np   = HN + n;

    for (int r = 0; r < 64; r++) {
        float cf[32];
        const float* cp = sC + r * 32;
        #pragma unroll
        for (int i = 0; i < 8; i++) {
            float4 v = *(const float4*)(cp + 4 * i);   // broadcast LDS.128
            cf[4*i+0] = v.x; cf[4*i+1] = v.y; cf[4*i+2] = v.z; cf[4*i+3] = v.w;
        }
        float Ee = 0.f, Eo = 0.f, Oe = 0.f, Oo = 0.f;
        #pragma unroll
        for (int j = 0; j < 8; j++) {
            Ee += cf[j]      * bas[j];
            Eo += cf[8 + j]  * bas[8 + j];
            Oe += cf[16 + j] * bas[16 + j];
            Oo += cf[24 + j] * bas[24 + j];
        }
        float P = Ee + Eo, Q = Ee - Eo, R = Oe + Oo, S = Oe - Oo;
        size_t rb = (size_t)(row0 + r) * NN;
        y[rb + n]    = P + R;
        y[rb + nrev] = P - R;
        y[rb + nm]   = Q - S;
        y[rb + np]   = Q + S;
    }
}

// Outputs n=2048, n=6144 (not covered by quartets): theta = pi*k/2.
__global__ void fix2048(float* __restrict__ y) {
    int row = blockIdx.x * blockDim.x + threadIdx.x;
    if (row >= ROWS) return;
    const float* c = g_C2 + (size_t)row * 32;
    float da = 0.f, db = 0.f;
    #pragma unroll
    for (int j = 0; j < 8; j++) {
        float s = (j & 1) ? -1.f : 1.f;
        da += s * c[j];        // A_{2j} * cos(pi j)
        db += s * c[24 + j];   // B_{2j+1} * (-1)^j
    }
    y[(size_t)row * NN + QN]     = da + db;
    y[(size_t)row * NN + 3 * QN] = da - db;
}

// ---------------------------------------------------------------------------
extern "C" void kernel_launch(void* const* d_in, const int* in_sizes, int n_in,
                              void* d_out, int out_size) {
    const float* x  = (const float*)d_in[0];
    const float* wr = (const float*)d_in[1];
    const float* wi = (const float*)d_in[2];
    float*       y  = (float*)d_out;

    init_basis<<<(QN * 32 + 255) / 256, 256>>>();
    fwd_dft<<<dim3(ROWS / 64, KSPL), 128>>>(x);
    mix<<<dim3(MODES, 64), 64>>>(x, wr, wi);
    fix2048<<<(ROWS + 255) / 256, 256>>>(y);
    inv_dft<<<dim3(QN / 256, ROWS / 64), 256>>>(y);
}